// round 16
// baseline (speedup 1.0000x reference)
#include <cuda_runtime.h>
#include <cuda_fp16.h>
#include <cstdint>

#define N_REFLNS 2000000
#define N_IMAGES 8192
#define N_RAC    1000000
#define MC       8
#define D_META   16
#define HIDDEN   32
#define LOG_2PI_F 1.8378770664093453f

// ---------------- scratch (static device globals; no allocation) ----------------
__device__ float4 g_zT[N_RAC * 2];       // z transposed: (N_RAC, 8)
__device__ float  g_img_sum[N_IMAGES];
__device__ float  g_img_cnt[N_IMAGES];
__device__ float  g_kl_sum;
__device__ float  g_ll_total;
__device__ unsigned g_done;

// ---------------- helpers ----------------
__device__ __forceinline__ void split_pair(float x, float y, unsigned& hi, unsigned& lo) {
    __half2 h = __floats2half2_rn(x, y);
    float2 hf = __half22float2(h);
    __half2 l = __floats2half2_rn(x - hf.x, y - hf.y);
    hi = *reinterpret_cast<unsigned*>(&h);
    lo = *reinterpret_cast<unsigned*>(&l);
}

__device__ __forceinline__ void mma16(float4& d,
                                      unsigned a0, unsigned a1, unsigned a2, unsigned a3,
                                      unsigned b0, unsigned b1) {
    asm("mma.sync.aligned.m16n8k16.row.col.f32.f16.f16.f32 "
        "{%0,%1,%2,%3}, {%4,%5,%6,%7}, {%8,%9}, {%0,%1,%2,%3};"
        : "+f"(d.x), "+f"(d.y), "+f"(d.z), "+f"(d.w)
        : "r"(a0), "r"(a1), "r"(a2), "r"(a3), "r"(b0), "r"(b1));
}

__device__ __forceinline__ float softplus_f(float x) {
    float ax = fabsf(x);
    float t  = __expf(-ax);
    float l  = (t > 0.0078125f) ? __logf(1.0f + t) : fmaf(-0.5f * t, t, t);
    return fmaxf(x, 0.0f) + l;
}

// ---------------- kernel 1: init + z transpose + KL ----------------
__global__ __launch_bounds__(256) void zkl_kernel(const float* __restrict__ q_loc,
                                                  const float* __restrict__ q_ls,
                                                  const float* __restrict__ eps) {
    int m = blockIdx.x * 256 + threadIdx.x;
    if (m < N_IMAGES) { g_img_sum[m] = 0.0f; g_img_cnt[m] = 0.0f; }
    if (m == 0) { g_kl_sum = 0.0f; g_ll_total = 0.0f; g_done = 0u; }
    float kl = 0.0f;
    if (m < N_RAC) {
        float loc = q_loc[m];
        float ls  = q_ls[m];
        float s   = __expf(ls);
        kl = fmaf(0.5f, fmaf(s, s, fmaf(loc, loc, -1.0f)), -ls);
        float z[8];
#pragma unroll
        for (int c = 0; c < 8; c++)
            z[c] = fmaf(s, __ldcs(eps + (size_t)c * N_RAC + m), loc);
        g_zT[2 * m]     = make_float4(z[0], z[1], z[2], z[3]);
        g_zT[2 * m + 1] = make_float4(z[4], z[5], z[6], z[7]);
    }
#pragma unroll
    for (int off = 16; off; off >>= 1)
        kl += __shfl_down_sync(0xffffffffu, kl, off);
    __shared__ float wsum[8];
    int lane = threadIdx.x & 31, wid = threadIdx.x >> 5;
    if (lane == 0) wsum[wid] = kl;
    __syncthreads();
    if (threadIdx.x == 0) {
        float t = 0.0f;
#pragma unroll
        for (int i = 0; i < 8; i++) t += wsum[i];
        atomicAdd(&g_kl_sum, t);
    }
}

// segmented warp reduce + atomic (image_id sorted; popc counts reflections/image)
__device__ __forceinline__ void seg_atomic(float v, int img, int lane) {
    unsigned mask = __match_any_sync(0xffffffffu, img);
    int hi = 31 - __clz(mask);
#pragma unroll
    for (int off = 1; off < 32; off <<= 1) {
        float o = __shfl_down_sync(0xffffffffu, v, off);
        if (lane + off <= hi) v += o;
    }
    if (lane == (__ffs(mask) - 1)) {
        atomicAdd(&g_img_sum[img], v);
        atomicAdd(&g_img_cnt[img], (float)__popc(mask));
    }
}

// ---------------- kernel 2: fp16x3 tensor MLP + SMEM-transpose epilogue ---------
// R13 core. Deltas: grid = one exact resident wave (740 blocks, 5/SM) to cut
// the 5-vs-6 chunk tail imbalance; layer2 uses 2 accumulators to halve the
// serial MMA dependency chain.
#define PB_STRIDE 12   // floats; 48B row stride, float4-aligned

__global__ __launch_bounds__(128, 5) void refl_kernel(const float* __restrict__ metadata,
                                                      const float* __restrict__ W1,
                                                      const float* __restrict__ b1,
                                                      const float* __restrict__ W2,
                                                      const float* __restrict__ b2,
                                                      const float* __restrict__ iobs,
                                                      const float* __restrict__ sigiobs,
                                                      const int*   __restrict__ image_id,
                                                      const int*   __restrict__ miller_id,
                                                      float*       __restrict__ out) {
    __shared__ __align__(16) float pbuf[4][32 * PB_STRIDE];

    int tid  = threadIdx.x;
    int w    = tid >> 5;
    int lane = tid & 31;
    int q    = lane >> 2;   // groupID: row within m16
    int tig  = lane & 3;    // thread-in-group
    float* pb = pbuf[w];

    // ---- weight fragments (hi/lo fp16), loaded once per warp ----
    unsigned w1h[4][2], w1l[4][2];
#pragma unroll
    for (int j = 0; j < 4; j++) {
        int col = 8 * j + q;
        split_pair(W1[(2 * tig) * HIDDEN + col],     W1[(2 * tig + 1) * HIDDEN + col], w1h[j][0], w1l[j][0]);
        split_pair(W1[(2 * tig + 8) * HIDDEN + col], W1[(2 * tig + 9) * HIDDEN + col], w1h[j][1], w1l[j][1]);
    }
    unsigned w2h[2][2], w2l[2][2];
#pragma unroll
    for (int s = 0; s < 2; s++) {
        int k0 = 16 * s + 2 * tig;
        split_pair(W2[k0 * MC + q],       W2[(k0 + 1) * MC + q], w2h[s][0], w2l[s][0]);
        split_pair(W2[(k0 + 8) * MC + q], W2[(k0 + 9) * MC + q], w2h[s][1], w2l[s][1]);
    }
    float b1x[4], b1y[4];
#pragma unroll
    for (int j = 0; j < 4; j++) { b1x[j] = b1[8 * j + 2 * tig]; b1y[j] = b1[8 * j + 2 * tig + 1]; }
    float b2x = b2[2 * tig], b2y = b2[2 * tig + 1];

    const int nchunks = N_REFLNS / 32;     // 62500 exact
    int gwarp  = blockIdx.x * 4 + w;
    int nwarps = gridDim.x * 4;

    for (int chunk = gwarp; chunk < nchunks; chunk += nwarps) {
        int base = chunk * 32;
        int rown = base + lane;

        // ---- owner loads: fully coalesced, zero redundancy ----
        int   mid_own = __ldcs(miller_id + rown);
        float io_own  = __ldcs(iobs + rown);
        float sg_own  = __ldcs(sigiobs + rown);
        int   img_own = __ldcs(image_id + rown);

        // ---- metadata loads (coalesced LDG.64 stream, evict-first) ----
        float2 va[2][4];
#pragma unroll
        for (int t = 0; t < 2; t++) {
            const float* Ma = metadata + (size_t)(base + 16 * t + q) * D_META;
            const float* Mb = metadata + (size_t)(base + 16 * t + q + 8) * D_META;
            va[t][0] = __ldcs((const float2*)(Ma + 2 * tig));
            va[t][1] = __ldcs((const float2*)(Mb + 2 * tig));
            va[t][2] = __ldcs((const float2*)(Ma + 2 * tig + 8));
            va[t][3] = __ldcs((const float2*)(Mb + 2 * tig + 8));
        }

        // ---- zT gather: owner-contiguous 32B (2x LDG.128), overlaps the MLP ----
        float4 f0 = g_zT[2 * mid_own];
        float4 f1 = g_zT[2 * mid_own + 1];

        // ---- compute both subtiles, stage p into per-warp SMEM ----
#pragma unroll
        for (int t = 0; t < 2; t++) {
            unsigned ah[4], al[4];
            split_pair(va[t][0].x, va[t][0].y, ah[0], al[0]);
            split_pair(va[t][1].x, va[t][1].y, ah[1], al[1]);
            split_pair(va[t][2].x, va[t][2].y, ah[2], al[2]);
            split_pair(va[t][3].x, va[t][3].y, ah[3], al[3]);

            // layer1: h = meta @ W1 + b1, 3-term fp16
            float4 acc[4];
#pragma unroll
            for (int j = 0; j < 4; j++) {
                acc[j] = make_float4(b1x[j], b1y[j], b1x[j], b1y[j]);
                mma16(acc[j], ah[0], ah[1], ah[2], ah[3], w1h[j][0], w1h[j][1]);
                mma16(acc[j], al[0], al[1], al[2], al[3], w1h[j][0], w1h[j][1]);
                mma16(acc[j], ah[0], ah[1], ah[2], ah[3], w1l[j][0], w1l[j][1]);
            }

            // layer2: p = relu(h) @ W2 + b2; 2 accumulators halve the MMA chain
            float4 p0 = make_float4(b2x, b2y, b2x, b2y);
            float4 p1 = make_float4(0.0f, 0.0f, 0.0f, 0.0f);
#pragma unroll
            for (int s = 0; s < 2; s++) {
                float4& ps = (s == 0) ? p0 : p1;
                const float4& cA = acc[2 * s];
                const float4& cB = acc[2 * s + 1];
                unsigned a2h[4], a2l[4];
                split_pair(fmaxf(cA.x, 0.0f), fmaxf(cA.y, 0.0f), a2h[0], a2l[0]);
                split_pair(fmaxf(cA.z, 0.0f), fmaxf(cA.w, 0.0f), a2h[1], a2l[1]);
                split_pair(fmaxf(cB.x, 0.0f), fmaxf(cB.y, 0.0f), a2h[2], a2l[2]);
                split_pair(fmaxf(cB.z, 0.0f), fmaxf(cB.w, 0.0f), a2h[3], a2l[3]);
                mma16(ps, a2h[0], a2h[1], a2h[2], a2h[3], w2h[s][0], w2h[s][1]);
                mma16(ps, a2l[0], a2l[1], a2l[2], a2l[3], w2h[s][0], w2h[s][1]);
                mma16(ps, a2h[0], a2h[1], a2h[2], a2h[3], w2l[s][0], w2l[s][1]);
            }
            float4 p = make_float4(p0.x + p1.x, p0.y + p1.y, p0.z + p1.z, p0.w + p1.w);
            // p: rows 16t+q (x,y) / 16t+q+8 (z,w); cols 2tig, 2tig+1
            *(float2*)&pb[(16 * t + q) * PB_STRIDE + 2 * tig]     = make_float2(p.x, p.y);
            *(float2*)&pb[(16 * t + q + 8) * PB_STRIDE + 2 * tig] = make_float2(p.z, p.w);
        }
        __syncwarp();

        // ---- owner epilogue: my reflection's 8 logits, contiguous ----
        float4 pa = *(float4*)&pb[lane * PB_STRIDE];
        float4 pc = *(float4*)&pb[lane * PB_STRIDE + 4];
        __syncwarp();   // reads done before next chunk's stores

        float pv[8] = {pa.x, pa.y, pa.z, pa.w, pc.x, pc.y, pc.z, pc.w};
        float fvv[8] = {f0.x, f0.y, f0.z, f0.w, f1.x, f1.y, f1.z, f1.w};

        float inv = 1.0f / sg_own;
        float si = 0.0f, ss = 0.0f;
#pragma unroll
        for (int c = 0; c < 8; c++) {
            float sc = softplus_f(pv[c]);
            float ip = fvv[c] * fvv[c] * sc;
            si += ip;
            float rr = (ip - io_own) * inv;
            ss = fmaf(rr, rr, ss);
        }

        // ONE coalesced store, ONE log, ONE seg_atomic
        __stcs(out + rown, si * 0.125f);
        float ll = fmaf(-0.5f, ss, -8.0f * (__logf(sg_own) + 0.5f * LOG_2PI_F));
        seg_atomic(ll, img_own, lane);
    }
}

// ---------------- kernel 3: parallel finalize (8 blocks, last writes scalars) ---
__global__ __launch_bounds__(1024) void finalize_kernel(float* __restrict__ out) {
    int i = blockIdx.x * 1024 + threadIdx.x;
    float v = g_img_sum[i] * (1.0f / fmaxf(g_img_cnt[i], 1.0f));
#pragma unroll
    for (int off = 16; off; off >>= 1)
        v += __shfl_down_sync(0xffffffffu, v, off);
    __shared__ float wsum[32];
    int lane = threadIdx.x & 31, wid = threadIdx.x >> 5;
    if (lane == 0) wsum[wid] = v;
    __syncthreads();
    if (wid == 0) {
        float t = wsum[lane];
#pragma unroll
        for (int off = 16; off; off >>= 1)
            t += __shfl_down_sync(0xffffffffu, t, off);
        if (lane == 0) {
            atomicAdd(&g_ll_total, t);
            __threadfence();
            unsigned ticket = atomicAdd(&g_done, 1u);
            if (ticket == gridDim.x - 1) {
                float total = atomicAdd(&g_ll_total, 0.0f);
                out[N_REFLNS]     = -(total / (float)MC) / (float)N_IMAGES;
                out[N_REFLNS + 1] = g_kl_sum * (1.0f / (float)N_RAC);
            }
        }
    }
}

// ---------------- launch ----------------
extern "C" void kernel_launch(void* const* d_in, const int* in_sizes, int n_in,
                              void* d_out, int out_size) {
    const float* q_loc     = (const float*)d_in[0];
    const float* q_ls      = (const float*)d_in[1];
    const float* eps       = (const float*)d_in[2];
    const float* metadata  = (const float*)d_in[3];
    const float* W1        = (const float*)d_in[4];
    const float* b1        = (const float*)d_in[5];
    const float* W2        = (const float*)d_in[6];
    const float* b2        = (const float*)d_in[7];
    const float* iobs      = (const float*)d_in[8];
    const float* sigiobs   = (const float*)d_in[9];
    const int*   image_id  = (const int*)d_in[10];
    const int*   miller_id = (const int*)d_in[11];
    float* out = (float*)d_out;

    zkl_kernel<<<(N_RAC + 255) / 256, 256>>>(q_loc, q_ls, eps);
    refl_kernel<<<740, 128>>>(metadata, W1, b1, W2, b2,
                              iobs, sigiobs, image_id, miller_id, out);
    finalize_kernel<<<N_IMAGES / 1024, 1024>>>(out);
}